// round 8
// baseline (speedup 1.0000x reference)
#include <cuda_runtime.h>

// NCC2D: -mean( cross^2 / (I_var*J_var + 1e-5) ), 9x9 zero-padded box sums.
// cross = IJ - I*J/81 ; I_var = I2 - I^2/81 ; J_var = J2 - J^2/81.
//
// Ring-free vertical-first formulation (round-7 structure), occupancy+ and
// guard-free interior strips:
//   grid (26 strips x 32 images) = 832 blocks, TPB=128 (full 512-col row,
//   4 cols/thread), launch_bounds(128,6) -> ~22 warps/SM, single wave.
//   Interior strips (0 < r0 <= 488): peeled warm-up + steady loop with NO
//   range checks (loads/subtracts provably in-range) -> ptxas batches LDGs.
//   Top/bottom strips: guarded generic loop (identical math).
//   Emit: V -> double-buffered smem row, 1 bar, neighbor read, 9-tap window.
//   Block partial -> double atomic; last block finalizes + resets.

#define BW   512
#define BH   512
#define NB   32
#define ROWS 20
#define TPB  128
#define STRIPS 26                    // 25 full strips of 20 + one of 12
#define NBLOCKS (STRIPS * NB)        // 832

__device__ double       g_acc;   // zero-init at load; reset by last block
__device__ unsigned int g_cnt;

struct NccState {
    float vI[4], vJ[4], vI2[4], vJ2[4], vIJ[4];
    float acc;
};

// Vertical running-sum update from packed new/old float4s.
__device__ __forceinline__ void vupdate(NccState& st,
                                        float4 a1, float4 b1,
                                        float4 ao, float4 bo) {
    const float an[4] = {a1.x, a1.y, a1.z, a1.w};
    const float bn[4] = {b1.x, b1.y, b1.z, b1.w};
    const float ap[4] = {ao.x, ao.y, ao.z, ao.w};
    const float bp[4] = {bo.x, bo.y, bo.z, bo.w};
#pragma unroll
    for (int c = 0; c < 4; ++c) {
        st.vI[c]  += an[c] - ap[c];
        st.vJ[c]  += bn[c] - bp[c];
        st.vI2[c]  = fmaf(an[c], an[c], fmaf(-ap[c], ap[c], st.vI2[c]));
        st.vJ2[c]  = fmaf(bn[c], bn[c], fmaf(-bp[c], bp[c], st.vJ2[c]));
        st.vIJ[c]  = fmaf(an[c], bn[c], fmaf(-ap[c], bp[c], st.vIJ[c]));
    }
}

// Emit one output row: exchange V via smem, 9-tap horizontal window, NCC.
__device__ __forceinline__ void emit_row(NccState& st,
                                         float4 (*sVb)[TPB],  // sV[buf]
                                         int t) {
    const float4 z = make_float4(0.f, 0.f, 0.f, 0.f);
    const float inv81 = 1.0f / 81.0f;

    sVb[0][t] = make_float4(st.vI[0],  st.vI[1],  st.vI[2],  st.vI[3]);
    sVb[1][t] = make_float4(st.vJ[0],  st.vJ[1],  st.vJ[2],  st.vJ[3]);
    sVb[2][t] = make_float4(st.vI2[0], st.vI2[1], st.vI2[2], st.vI2[3]);
    sVb[3][t] = make_float4(st.vJ2[0], st.vJ2[1], st.vJ2[2], st.vJ2[3]);
    sVb[4][t] = make_float4(st.vIJ[0], st.vIJ[1], st.vIJ[2], st.vIJ[3]);
    __syncthreads();

    float box[5][4];
    const float* own[5] = {st.vI, st.vJ, st.vI2, st.vJ2, st.vIJ};
#pragma unroll
    for (int p = 0; p < 5; ++p) {
        float4 L = (t > 0)       ? sVb[p][t - 1] : z;
        float4 R = (t < TPB - 1) ? sVb[p][t + 1] : z;
        float v0 = L.x, v1 = L.y, v2 = L.z, v3 = L.w;
        float v4 = own[p][0], v5 = own[p][1], v6 = own[p][2], v7 = own[p][3];
        float v8 = R.x, v9 = R.y, v10 = R.z, v11 = R.w;
        float w = ((v0 + v1) + (v2 + v3)) + ((v4 + v5) + (v6 + v7)) + v8;
        box[p][0] = w;
        box[p][1] = w = w - v0 + v9;
        box[p][2] = w = w - v1 + v10;
        box[p][3] =     w - v2 + v11;
    }
#pragma unroll
    for (int c = 0; c < 4; ++c) {
        float sI = box[0][c], sJ = box[1][c];
        float cross = fmaf(sI * sJ, -inv81, box[4][c]);
        float Iv    = fmaf(sI * sI, -inv81, box[2][c]);
        float Jv    = fmaf(sJ * sJ, -inv81, box[3][c]);
        float den   = fmaf(Iv, Jv, 1e-5f);
        st.acc += __fdividef(cross * cross, den);
    }
}

__global__ __launch_bounds__(TPB, 6) void ncc_main_k(const float* __restrict__ gI,
                                                     const float* __restrict__ gJ,
                                                     float* __restrict__ out) {
    __shared__ float4 sV[2][5][TPB];     // double-buffered V exchange: 20480 B
    __shared__ float  wsum[TPB / 32];

    const int t    = threadIdx.x;
    const int lane = t & 31;
    const int r0   = blockIdx.x * ROWS;
    const size_t img = (size_t)blockIdx.y * ((size_t)BH * BW);
    const float4 z = make_float4(0.f, 0.f, 0.f, 0.f);

    const float4* bI = (const float4*)(gI + img) + t;   // column base, stride BW/4
    const float4* bJ = (const float4*)(gJ + img) + t;

    NccState st;
#pragma unroll
    for (int c = 0; c < 4; ++c) {
        st.vI[c] = st.vJ[c] = st.vI2[c] = st.vJ2[c] = st.vIJ[c] = 0.f;
    }
    st.acc = 0.f;

    if (r0 > 0 && r0 <= BH - ROWS - 4) {
        // ---------- interior strip: zero range checks ----------
        // Warm-up: add rows r0-4 .. r0+3 (8 rows), no subtract, no emit.
#pragma unroll
        for (int it = 0; it < 8; ++it) {
            const int rn = r0 - 4 + it;
            vupdate(st, __ldg(bI + (size_t)rn * (BW / 4)),
                        __ldg(bJ + (size_t)rn * (BW / 4)), z, z);
        }
        // it = 8: add row r0+4 (window full), no subtract, emit row r0.
        {
            const int rn = r0 + 4;
            vupdate(st, __ldg(bI + (size_t)rn * (BW / 4)),
                        __ldg(bJ + (size_t)rn * (BW / 4)), z, z);
            emit_row(st, sV[0], t);
        }
        // Steady: it = 9..27 — unconditional add of rn and subtract of rn-9.
#pragma unroll 2
        for (int it = 9; it < ROWS + 8; ++it) {
            const int rn = r0 - 4 + it;
            const int ro = rn - 9;
            float4 a1 = __ldg(bI + (size_t)rn * (BW / 4));
            float4 b1 = __ldg(bJ + (size_t)rn * (BW / 4));
            float4 ao = __ldg(bI + (size_t)ro * (BW / 4));
            float4 bo = __ldg(bJ + (size_t)ro * (BW / 4));
            vupdate(st, a1, b1, ao, bo);
            emit_row(st, sV[it & 1], t);
        }
    } else {
        // ---------- top / bottom strip: guarded generic loop ----------
        const int rows_eff = min(ROWS, BH - r0);
        const int iters = rows_eff + 8;
        for (int it = 0; it < iters; ++it) {
            const int rn = r0 - 4 + it;
            const int ro = rn - 9;
            float4 a1 = z, b1 = z, ao = z, bo = z;
            if (rn >= 0 && rn < BH) {
                a1 = __ldg(bI + (size_t)rn * (BW / 4));
                b1 = __ldg(bJ + (size_t)rn * (BW / 4));
            }
            if (it >= 9 && ro >= 0) {   // only rows actually added earlier
                ao = __ldg(bI + (size_t)ro * (BW / 4));
                bo = __ldg(bJ + (size_t)ro * (BW / 4));
            }
            vupdate(st, a1, b1, ao, bo);
            if (it >= 8) emit_row(st, sV[it & 1], t);
        }
    }

    // Block reduction -> global double atomic; last block finalizes + resets.
    float acc = st.acc;
#pragma unroll
    for (int o = 16; o; o >>= 1) acc += __shfl_xor_sync(0xffffffffu, acc, o);
    if (lane == 0) wsum[t >> 5] = acc;
    __syncthreads();
    if (t == 0) {
        float bs = 0.f;
#pragma unroll
        for (int w = 0; w < TPB / 32; ++w) bs += wsum[w];
        atomicAdd(&g_acc, (double)bs);
        __threadfence();
        unsigned int done = atomicAdd(&g_cnt, 1u);
        if (done == NBLOCKS - 1) {
            __threadfence();
            double v = *((volatile double*)&g_acc);
            out[0] = (float)(-v * (1.0 / (double)((long long)NB * BH * BW)));
            g_acc = 0.0;          // reset for next graph replay
            g_cnt = 0u;
        }
    }
}

extern "C" void kernel_launch(void* const* d_in, const int* in_sizes, int n_in,
                              void* d_out, int out_size) {
    const float* I = (const float*)d_in[0];
    const float* J = (const float*)d_in[1];
    float* out = (float*)d_out;

    dim3 grid(STRIPS, NB);   // (26, 32) = 832 blocks, single wave at 6/SM
    ncc_main_k<<<grid, TPB>>>(I, J, out);
}

// round 9
// speedup vs baseline: 1.2000x; 1.2000x over previous
#include <cuda_runtime.h>

// NCC2D: -mean( cross^2 / (I_var*J_var + 1e-5) ), 9x9 zero-padded box sums.
// cross = IJ - I*J/81 ; I_var = I2 - I^2/81 ; J_var = J2 - J^2/81.
//
// Round-7 body verbatim (proven codegen: named register arrays, DO_WIN macro,
// guarded loop) + occupancy bump only:
//   grid (26 strips x 32 images) = 832 blocks, TPB=128, 4 cols/thread.
//   launch_bounds(128,6) -> ~22 warps/SM resident, single wave (<= 888).
//   Per ingested row: load own float4 of I,J at rn (new) and rn-9 (old, L2
//   hit), update per-column vertical running sums in registers; subtract only
//   rows actually added (it >= 9). Emit: V -> double-buffered smem row,
//   1 bar, neighbor read, 9-tap horizontal window -> NCC term.
//   Block partial -> double atomic; last block finalizes + resets.

#define BW   512
#define BH   512
#define NB   32
#define ROWS 20
#define TPB  128
#define STRIPS 26                    // 25 full strips of 20 + one of 12
#define NBLOCKS (STRIPS * NB)        // 832

__device__ double       g_acc;   // zero-init at load; reset by last block
__device__ unsigned int g_cnt;

__global__ __launch_bounds__(TPB, 6) void ncc_main_k(const float* __restrict__ gI,
                                                     const float* __restrict__ gJ,
                                                     float* __restrict__ out) {
    __shared__ float4 sV[2][5][TPB];     // double-buffered V exchange: 20480 B
    __shared__ float  wsum[TPB / 32];

    const int t    = threadIdx.x;
    const int lane = t & 31;
    const int r0   = blockIdx.x * ROWS;
    const int rows_eff = min(ROWS, BH - r0);
    const size_t img = (size_t)blockIdx.y * ((size_t)BH * BW);
    const float4 z = make_float4(0.f, 0.f, 0.f, 0.f);
    const float inv81 = 1.0f / 81.0f;

    float vI[4]  = {0.f, 0.f, 0.f, 0.f};
    float vJ[4]  = {0.f, 0.f, 0.f, 0.f};
    float vI2[4] = {0.f, 0.f, 0.f, 0.f};
    float vJ2[4] = {0.f, 0.f, 0.f, 0.f};
    float vIJ[4] = {0.f, 0.f, 0.f, 0.f};
    float acc = 0.f;

    const int iters = rows_eff + 8;
#pragma unroll 2
    for (int it = 0; it < iters; ++it) {
        const int rn = r0 - 4 + it;      // new row entering the window
        const int ro = rn - 9;           // old row leaving the window

        float4 a1 = z, b1 = z, ao = z, bo = z;
        if (rn >= 0 && rn < BH) {
            a1 = __ldg((const float4*)(gI + img + (size_t)rn * BW) + t);
            b1 = __ldg((const float4*)(gJ + img + (size_t)rn * BW) + t);
        }
        // Old row must have been ADDED earlier (it >= 9) and be a real row.
        if (it >= 9 && ro >= 0) {
            ao = __ldg((const float4*)(gI + img + (size_t)ro * BW) + t);
            bo = __ldg((const float4*)(gJ + img + (size_t)ro * BW) + t);
        }
        const float an[4] = {a1.x, a1.y, a1.z, a1.w};
        const float bn[4] = {b1.x, b1.y, b1.z, b1.w};
        const float ap[4] = {ao.x, ao.y, ao.z, ao.w};
        const float bp[4] = {bo.x, bo.y, bo.z, bo.w};
#pragma unroll
        for (int c = 0; c < 4; ++c) {
            vI[c] += an[c] - ap[c];
            vJ[c] += bn[c] - bp[c];
            vI2[c] = fmaf(an[c], an[c], fmaf(-ap[c], ap[c], vI2[c]));
            vJ2[c] = fmaf(bn[c], bn[c], fmaf(-bp[c], bp[c], vJ2[c]));
            vIJ[c] = fmaf(an[c], bn[c], fmaf(-ap[c], bp[c], vIJ[c]));
        }

        if (it >= 8) {                   // output row y = rn - 4 is complete
            const int buf = it & 1;
            sV[buf][0][t] = make_float4(vI[0],  vI[1],  vI[2],  vI[3]);
            sV[buf][1][t] = make_float4(vJ[0],  vJ[1],  vJ[2],  vJ[3]);
            sV[buf][2][t] = make_float4(vI2[0], vI2[1], vI2[2], vI2[3]);
            sV[buf][3][t] = make_float4(vJ2[0], vJ2[1], vJ2[2], vJ2[3]);
            sV[buf][4][t] = make_float4(vIJ[0], vIJ[1], vIJ[2], vIJ[3]);
            __syncthreads();

            float box[5][4];
#define DO_WIN(P, VA)                                                          \
            {                                                                  \
                float4 L = (t > 0)       ? sV[buf][P][t - 1] : z;              \
                float4 R = (t < TPB - 1) ? sV[buf][P][t + 1] : z;              \
                float v0 = L.x, v1 = L.y, v2 = L.z, v3 = L.w;                  \
                float v4 = VA[0], v5 = VA[1], v6 = VA[2], v7 = VA[3];          \
                float v8 = R.x, v9 = R.y, v10 = R.z, v11 = R.w;                \
                float w = ((v0 + v1) + (v2 + v3))                              \
                        + ((v4 + v5) + (v6 + v7)) + v8;                        \
                box[P][0] = w;                                                 \
                box[P][1] = w = w - v0 + v9;                                   \
                box[P][2] = w = w - v1 + v10;                                  \
                box[P][3] =     w - v2 + v11;                                  \
            }
            DO_WIN(0, vI)
            DO_WIN(1, vJ)
            DO_WIN(2, vI2)
            DO_WIN(3, vJ2)
            DO_WIN(4, vIJ)
#undef DO_WIN

#pragma unroll
            for (int c = 0; c < 4; ++c) {
                float sI = box[0][c], sJ = box[1][c];
                float cross = fmaf(sI * sJ, -inv81, box[4][c]);
                float Iv    = fmaf(sI * sI, -inv81, box[2][c]);
                float Jv    = fmaf(sJ * sJ, -inv81, box[3][c]);
                float den   = fmaf(Iv, Jv, 1e-5f);
                acc += __fdividef(cross * cross, den);
            }
        }
    }

    // Block reduction -> global double atomic; last block finalizes + resets.
#pragma unroll
    for (int o = 16; o; o >>= 1) acc += __shfl_xor_sync(0xffffffffu, acc, o);
    if (lane == 0) wsum[t >> 5] = acc;
    __syncthreads();
    if (t == 0) {
        float bs = 0.f;
#pragma unroll
        for (int w = 0; w < TPB / 32; ++w) bs += wsum[w];
        atomicAdd(&g_acc, (double)bs);
        __threadfence();
        unsigned int done = atomicAdd(&g_cnt, 1u);
        if (done == NBLOCKS - 1) {
            __threadfence();
            double v = *((volatile double*)&g_acc);
            out[0] = (float)(-v * (1.0 / (double)((long long)NB * BH * BW)));
            g_acc = 0.0;          // reset for next graph replay
            g_cnt = 0u;
        }
    }
}

extern "C" void kernel_launch(void* const* d_in, const int* in_sizes, int n_in,
                              void* d_out, int out_size) {
    const float* I = (const float*)d_in[0];
    const float* J = (const float*)d_in[1];
    float* out = (float*)d_out;

    dim3 grid(STRIPS, NB);   // (26, 32) = 832 blocks, single wave at 6/SM
    ncc_main_k<<<grid, TPB>>>(I, J, out);
}

// round 10
// speedup vs baseline: 1.6199x; 1.3499x over previous
#include <cuda_runtime.h>

// NCC2D: -mean( cross^2 / (I_var*J_var + 1e-5) ), 9x9 zero-padded box sums.
// cross = IJ - I*J/81 ; I_var = I2 - I^2/81 ; J_var = J2 - J^2/81.
//
// Base: round-7 winner config (bench 32.8us): ROWS=24, 22 strips x 32 images
// = 704 blocks, TPB=128 (full 512-col row, 4 cols/thread), lb(128,5),
// double-buffered smem V exchange (20KB), guarded generic loop.
// This round: interior strips (24 <= r0 <= 484, i.e. 20 of 22) take a PEELED
// guard-free path — unconditional warm-up adds + steady loop with no range
// checks — written with named register arrays + macros only (no structs, no
// pointer arrays; round-8's local-memory pitfall avoided). Edge strips keep
// the proven guarded loop. Math byte-identical to round 7.

#define BW   512
#define BH   512
#define NB   32
#define ROWS 24
#define TPB  128
#define STRIPS 22                    // 21 full strips of 24 + one of 8
#define NBLOCKS (STRIPS * NB)        // 704

__device__ double       g_acc;   // zero-init at load; reset by last block
__device__ unsigned int g_cnt;

__global__ __launch_bounds__(TPB, 5) void ncc_main_k(const float* __restrict__ gI,
                                                     const float* __restrict__ gJ,
                                                     float* __restrict__ out) {
    __shared__ float4 sV[2][5][TPB];     // double-buffered V exchange: 20480 B
    __shared__ float  wsum[TPB / 32];

    const int t    = threadIdx.x;
    const int lane = t & 31;
    const int r0   = blockIdx.x * ROWS;
    const size_t img = (size_t)blockIdx.y * ((size_t)BH * BW);
    const float4 z = make_float4(0.f, 0.f, 0.f, 0.f);
    const float inv81 = 1.0f / 81.0f;

    const float4* bI = (const float4*)(gI + img) + t;   // stride BW/4 per row
    const float4* bJ = (const float4*)(gJ + img) + t;

    float vI[4]  = {0.f, 0.f, 0.f, 0.f};
    float vJ[4]  = {0.f, 0.f, 0.f, 0.f};
    float vI2[4] = {0.f, 0.f, 0.f, 0.f};
    float vJ2[4] = {0.f, 0.f, 0.f, 0.f};
    float vIJ[4] = {0.f, 0.f, 0.f, 0.f};
    float acc = 0.f;

// Vertical running-sum update from float4s A1,B1 (new) and AO,BO (old).
#define VUPDATE(A1, B1, AO, BO)                                                \
    {                                                                          \
        const float an[4] = {(A1).x, (A1).y, (A1).z, (A1).w};                  \
        const float bn[4] = {(B1).x, (B1).y, (B1).z, (B1).w};                  \
        const float ap[4] = {(AO).x, (AO).y, (AO).z, (AO).w};                  \
        const float bp[4] = {(BO).x, (BO).y, (BO).z, (BO).w};                  \
        _Pragma("unroll")                                                      \
        for (int c = 0; c < 4; ++c) {                                          \
            vI[c] += an[c] - ap[c];                                            \
            vJ[c] += bn[c] - bp[c];                                            \
            vI2[c] = fmaf(an[c], an[c], fmaf(-ap[c], ap[c], vI2[c]));          \
            vJ2[c] = fmaf(bn[c], bn[c], fmaf(-bp[c], bp[c], vJ2[c]));          \
            vIJ[c] = fmaf(an[c], bn[c], fmaf(-ap[c], bp[c], vIJ[c]));          \
        }                                                                      \
    }

// Emit one output row via smem exchange buffer BUF (0/1).
#define EMIT(BUF)                                                              \
    {                                                                          \
        const int buf = (BUF);                                                 \
        sV[buf][0][t] = make_float4(vI[0],  vI[1],  vI[2],  vI[3]);            \
        sV[buf][1][t] = make_float4(vJ[0],  vJ[1],  vJ[2],  vJ[3]);            \
        sV[buf][2][t] = make_float4(vI2[0], vI2[1], vI2[2], vI2[3]);           \
        sV[buf][3][t] = make_float4(vJ2[0], vJ2[1], vJ2[2], vJ2[3]);           \
        sV[buf][4][t] = make_float4(vIJ[0], vIJ[1], vIJ[2], vIJ[3]);           \
        __syncthreads();                                                       \
        float box[5][4];                                                       \
        DO_WIN(0, vI)                                                          \
        DO_WIN(1, vJ)                                                          \
        DO_WIN(2, vI2)                                                         \
        DO_WIN(3, vJ2)                                                         \
        DO_WIN(4, vIJ)                                                         \
        _Pragma("unroll")                                                      \
        for (int c = 0; c < 4; ++c) {                                          \
            float sI = box[0][c], sJ = box[1][c];                              \
            float cross = fmaf(sI * sJ, -inv81, box[4][c]);                    \
            float Iv    = fmaf(sI * sI, -inv81, box[2][c]);                    \
            float Jv    = fmaf(sJ * sJ, -inv81, box[3][c]);                    \
            float den   = fmaf(Iv, Jv, 1e-5f);                                 \
            acc += __fdividef(cross * cross, den);                             \
        }                                                                      \
    }

#define DO_WIN(P, VA)                                                          \
    {                                                                          \
        float4 L = (t > 0)       ? sV[buf][P][t - 1] : z;                      \
        float4 R = (t < TPB - 1) ? sV[buf][P][t + 1] : z;                      \
        float v0 = L.x, v1 = L.y, v2 = L.z, v3 = L.w;                          \
        float v4 = VA[0], v5 = VA[1], v6 = VA[2], v7 = VA[3];                  \
        float v8 = R.x, v9 = R.y, v10 = R.z, v11 = R.w;                        \
        float w = ((v0 + v1) + (v2 + v3)) + ((v4 + v5) + (v6 + v7)) + v8;      \
        box[P][0] = w;                                                         \
        box[P][1] = w = w - v0 + v9;                                           \
        box[P][2] = w = w - v1 + v10;                                          \
        box[P][3] =     w - v2 + v11;                                          \
    }

    if (r0 >= ROWS && r0 + ROWS + 4 <= BH) {
        // ---------- interior strip (20 of 22): zero range checks ----------
        // Warm-up: add rows r0-4 .. r0+3 (all in-range), no subtract, no emit.
#pragma unroll
        for (int it = 0; it < 8; ++it) {
            const int rn = r0 - 4 + it;
            float4 a1 = __ldg(bI + (size_t)rn * (BW / 4));
            float4 b1 = __ldg(bJ + (size_t)rn * (BW / 4));
            VUPDATE(a1, b1, z, z)
        }
        // it = 8: window full, first emit (buf 0), still no subtract.
        {
            float4 a1 = __ldg(bI + (size_t)(r0 + 4) * (BW / 4));
            float4 b1 = __ldg(bJ + (size_t)(r0 + 4) * (BW / 4));
            VUPDATE(a1, b1, z, z)
            EMIT(0)
        }
        // Steady: it = 9..ROWS+7 — all loads/subtracts provably in-range.
#pragma unroll 2
        for (int it = 9; it < ROWS + 8; ++it) {
            const int rn = r0 - 4 + it;
            const int ro = rn - 9;
            float4 a1 = __ldg(bI + (size_t)rn * (BW / 4));
            float4 b1 = __ldg(bJ + (size_t)rn * (BW / 4));
            float4 ao = __ldg(bI + (size_t)ro * (BW / 4));
            float4 bo = __ldg(bJ + (size_t)ro * (BW / 4));
            VUPDATE(a1, b1, ao, bo)
            EMIT(it & 1)
        }
    } else {
        // ---------- edge strips: guarded generic loop (round-7 verbatim) ----
        const int rows_eff = min(ROWS, BH - r0);
        const int iters = rows_eff + 8;
#pragma unroll 2
        for (int it = 0; it < iters; ++it) {
            const int rn = r0 - 4 + it;
            const int ro = rn - 9;
            float4 a1 = z, b1 = z, ao = z, bo = z;
            if (rn >= 0 && rn < BH) {
                a1 = __ldg(bI + (size_t)rn * (BW / 4));
                b1 = __ldg(bJ + (size_t)rn * (BW / 4));
            }
            if (it >= 9 && ro >= 0) {   // only rows actually added earlier
                ao = __ldg(bI + (size_t)ro * (BW / 4));
                bo = __ldg(bJ + (size_t)ro * (BW / 4));
            }
            VUPDATE(a1, b1, ao, bo)
            if (it >= 8) EMIT(it & 1)
        }
    }
#undef DO_WIN
#undef EMIT
#undef VUPDATE

    // Block reduction -> global double atomic; last block finalizes + resets.
#pragma unroll
    for (int o = 16; o; o >>= 1) acc += __shfl_xor_sync(0xffffffffu, acc, o);
    if (lane == 0) wsum[t >> 5] = acc;
    __syncthreads();
    if (t == 0) {
        float bs = 0.f;
#pragma unroll
        for (int w = 0; w < TPB / 32; ++w) bs += wsum[w];
        atomicAdd(&g_acc, (double)bs);
        __threadfence();
        unsigned int done = atomicAdd(&g_cnt, 1u);
        if (done == NBLOCKS - 1) {
            __threadfence();
            double v = *((volatile double*)&g_acc);
            out[0] = (float)(-v * (1.0 / (double)((long long)NB * BH * BW)));
            g_acc = 0.0;          // reset for next graph replay
            g_cnt = 0u;
        }
    }
}

extern "C" void kernel_launch(void* const* d_in, const int* in_sizes, int n_in,
                              void* d_out, int out_size) {
    const float* I = (const float*)d_in[0];
    const float* J = (const float*)d_in[1];
    float* out = (float*)d_out;

    dim3 grid(STRIPS, NB);   // (22, 32) = 704 blocks, single wave at 5/SM
    ncc_main_k<<<grid, TPB>>>(I, J, out);
}